// round 1
// baseline (speedup 1.0000x reference)
#include <cuda_runtime.h>
#include <math.h>

// Problem constants (match setup_inputs)
#define BATCH 2
#define TSEQ  2048
#define DMODEL 1024
#define NHEADS 16
#define HDIM  64
#define ROWS (BATCH * TSEQ)          // 4096
#define QKV_N (3 * DMODEL)           // 3072

// ---------------- scratch (no allocation allowed) ----------------
__device__ float g_qkv[ROWS * QKV_N];              // [B*T, 3*D]  (~50MB)
__device__ float g_q[BATCH * NHEADS * TSEQ * HDIM]; // [B,H,T,Dh]
__device__ float g_k[BATCH * NHEADS * TSEQ * HDIM];
__device__ float g_v[BATCH * NHEADS * TSEQ * HDIM];
__device__ float g_attn[ROWS * DMODEL];            // [B*T, D]
__device__ float g_cs[TSEQ * 32 * 2];              // cos,sin per (t, freq)

// ---------------- tiled fp32 GEMM: C = A[M,K] @ B[N,K]^T + bias ----------------
#define BM 128
#define BN 128
#define BKD 8
#define TM 8
#define TN 8

template<int M, int N, int K>
__device__ __forceinline__ void gemm_body(const float* __restrict__ A,
                                          const float* __restrict__ B,
                                          const float* __restrict__ bias,
                                          float* __restrict__ C)
{
    __shared__ float As[BKD][BM];
    __shared__ float Bs[BKD][BN];

    const int tid = threadIdx.x;           // 256 threads
    const int tx = tid & 15;               // col group
    const int ty = tid >> 4;               // row group
    const int bm = blockIdx.y * BM;
    const int bn = blockIdx.x * BN;

    const int lrow = tid >> 1;             // 0..127
    const int lk4  = (tid & 1) * 4;        // 0 or 4

    const float* Aptr = A + (size_t)(bm + lrow) * K + lk4;
    const float* Bptr = B + (size_t)(bn + lrow) * K + lk4;

    float acc[TM][TN];
    #pragma unroll
    for (int m = 0; m < TM; m++)
        #pragma unroll
        for (int n = 0; n < TN; n++)
            acc[m][n] = 0.f;

    for (int k0 = 0; k0 < K; k0 += BKD) {
        float4 av = *(const float4*)(Aptr + k0);
        float4 bv = *(const float4*)(Bptr + k0);
        As[lk4 + 0][lrow] = av.x; As[lk4 + 1][lrow] = av.y;
        As[lk4 + 2][lrow] = av.z; As[lk4 + 3][lrow] = av.w;
        Bs[lk4 + 0][lrow] = bv.x; Bs[lk4 + 1][lrow] = bv.y;
        Bs[lk4 + 2][lrow] = bv.z; Bs[lk4 + 3][lrow] = bv.w;
        __syncthreads();

        #pragma unroll
        for (int k = 0; k < BKD; k++) {
            float ra[TM], rb[TN];
            float4 a0 = *(const float4*)&As[k][ty * TM];
            float4 a1 = *(const float4*)&As[k][ty * TM + 4];
            ra[0]=a0.x; ra[1]=a0.y; ra[2]=a0.z; ra[3]=a0.w;
            ra[4]=a1.x; ra[5]=a1.y; ra[6]=a1.z; ra[7]=a1.w;
            float4 b0 = *(const float4*)&Bs[k][tx * TN];
            float4 b1 = *(const float4*)&Bs[k][tx * TN + 4];
            rb[0]=b0.x; rb[1]=b0.y; rb[2]=b0.z; rb[3]=b0.w;
            rb[4]=b1.x; rb[5]=b1.y; rb[6]=b1.z; rb[7]=b1.w;
            #pragma unroll
            for (int m = 0; m < TM; m++)
                #pragma unroll
                for (int n = 0; n < TN; n++)
                    acc[m][n] = fmaf(ra[m], rb[n], acc[m][n]);
        }
        __syncthreads();
    }

    // epilogue with bias
    #pragma unroll
    for (int m = 0; m < TM; m++) {
        const int row = bm + ty * TM + m;
        float* cp = C + (size_t)row * N + bn + tx * TN;
        const float* bp = bias + bn + tx * TN;
        #pragma unroll
        for (int n = 0; n < TN; n += 4) {
            float4 o;
            o.x = acc[m][n + 0] + bp[n + 0];
            o.y = acc[m][n + 1] + bp[n + 1];
            o.z = acc[m][n + 2] + bp[n + 2];
            o.w = acc[m][n + 3] + bp[n + 3];
            *(float4*)(cp + n) = o;
        }
    }
}

__global__ __launch_bounds__(256) void qkv_gemm_kernel(const float* __restrict__ x,
                                                       const float* __restrict__ w,
                                                       const float* __restrict__ b)
{
    gemm_body<ROWS, QKV_N, DMODEL>(x, w, b, g_qkv);
}

__global__ __launch_bounds__(256) void proj_gemm_kernel(const float* __restrict__ w,
                                                        const float* __restrict__ b,
                                                        float* __restrict__ out)
{
    gemm_body<ROWS, DMODEL, DMODEL>(g_attn, w, b, out);
}

// ---------------- RoPE table: cos/sin of fp32 angle (double sincos for accuracy) --------
__global__ void rope_table_kernel()
{
    int idx = blockIdx.x * blockDim.x + threadIdx.x;
    if (idx >= TSEQ * 32) return;
    int t = idx >> 5;
    int j = idx & 31;
    // match reference: inv_freq = 1/10000^(2j/64) in fp32, angle = t * inv_freq in fp32
    float invf = powf(10000.0f, -((float)(2 * j) / 64.0f));
    float angle = (float)t * invf;
    double a = (double)angle;
    double s, c;
    sincos(a, &s, &c);
    g_cs[idx * 2 + 0] = (float)c;
    g_cs[idx * 2 + 1] = (float)s;
}

// ---------------- RoPE apply + transpose to [B,H,T,Dh] ----------------
__global__ void rope_apply_kernel()
{
    int idx = blockIdx.x * blockDim.x + threadIdx.x;
    if (idx >= BATCH * TSEQ * NHEADS * 32) return;
    int j = idx & 31;
    int h = (idx >> 5) & (NHEADS - 1);
    int t = (idx >> 9) & (TSEQ - 1);
    int b = idx >> 20;

    int row = b * TSEQ + t;
    const float* base = g_qkv + (size_t)row * QKV_N + h * HDIM;

    float c  = g_cs[(t * 32 + j) * 2 + 0];
    float sn = g_cs[(t * 32 + j) * 2 + 1];

    float q1 = base[j],          q2 = base[j + 32];
    float k1 = base[DMODEL + j], k2 = base[DMODEL + j + 32];

    size_t od = (((size_t)b * NHEADS + h) * TSEQ + t) * HDIM;
    g_q[od + j]      = q1 * c - q2 * sn;
    g_q[od + j + 32] = q2 * c + q1 * sn;
    g_k[od + j]      = k1 * c - k2 * sn;
    g_k[od + j + 32] = k2 * c + k1 * sn;
    g_v[od + j]      = base[2 * DMODEL + j];
    g_v[od + j + 32] = base[2 * DMODEL + j + 32];
}

// ---------------- flash attention (fp32, causal, online softmax) ----------------
#define BQ 128
#define BKV 32

__global__ __launch_bounds__(BQ) void flash_kernel()
{
    const int tid = threadIdx.x;
    const int qt = (gridDim.x - 1) - blockIdx.x;    // heaviest tiles first
    const int h = blockIdx.y;
    const int b = blockIdx.z;
    const int qi = qt * BQ + tid;

    const size_t bh = ((size_t)b * NHEADS + h) * TSEQ * HDIM;

    __shared__ float Ks[BKV * HDIM];
    __shared__ float Vs[BKV * HDIM];

    // query row in registers
    float4 q4[16];
    const float4* qp = (const float4*)(g_q + bh + (size_t)qi * HDIM);
    #pragma unroll
    for (int i = 0; i < 16; i++) q4[i] = qp[i];

    float acc[HDIM];
    #pragma unroll
    for (int d = 0; d < HDIM; d++) acc[d] = 0.f;
    float m = -INFINITY, l = 0.f;
    const float scale = 0.125f;   // 1/sqrt(64)

    const int ntiles = qt * (BQ / BKV) + (BQ / BKV);
    for (int t0 = 0; t0 < ntiles; t0++) {
        const int j0 = t0 * BKV;
        // cooperative load K/V tile (32x64 floats each)
        const float4* ksrc = (const float4*)(g_k + bh + (size_t)j0 * HDIM);
        const float4* vsrc = (const float4*)(g_v + bh + (size_t)j0 * HDIM);
        float4* kdst = (float4*)Ks;
        float4* vdst = (float4*)Vs;
        #pragma unroll
        for (int r = 0; r < 4; r++) {
            kdst[tid + BQ * r] = ksrc[tid + BQ * r];
            vdst[tid + BQ * r] = vsrc[tid + BQ * r];
        }
        __syncthreads();

        if (qi >= j0) {
            float s[BKV];
            float mt = m;
            #pragma unroll
            for (int j = 0; j < BKV; j++) {
                const float4* kr = (const float4*)(Ks + j * HDIM);
                float sum = 0.f;
                #pragma unroll
                for (int d = 0; d < 16; d++) {
                    float4 kk = kr[d];
                    sum = fmaf(q4[d].x, kk.x, sum);
                    sum = fmaf(q4[d].y, kk.y, sum);
                    sum = fmaf(q4[d].z, kk.z, sum);
                    sum = fmaf(q4[d].w, kk.w, sum);
                }
                s[j] = sum * scale;
                if (j0 + j <= qi) mt = fmaxf(mt, s[j]);
            }
            float corr = expf(m - mt);   // m=-inf first tile -> corr=0
            m = mt;
            l *= corr;
            #pragma unroll
            for (int d = 0; d < HDIM; d++) acc[d] *= corr;

            #pragma unroll
            for (int j = 0; j < BKV; j++) {
                float p = (j0 + j <= qi) ? expf(s[j] - mt) : 0.f;
                l += p;
                const float4* vr = (const float4*)(Vs + j * HDIM);
                #pragma unroll
                for (int d = 0; d < 16; d++) {
                    float4 vv = vr[d];
                    acc[4 * d + 0] = fmaf(p, vv.x, acc[4 * d + 0]);
                    acc[4 * d + 1] = fmaf(p, vv.y, acc[4 * d + 1]);
                    acc[4 * d + 2] = fmaf(p, vv.z, acc[4 * d + 2]);
                    acc[4 * d + 3] = fmaf(p, vv.w, acc[4 * d + 3]);
                }
            }
        }
        __syncthreads();
    }

    // write O as [B, T, H, Dh] == [B*T, D] rows for proj GEMM
    const float inv_l = 1.f / l;
    float* op = g_attn + (((size_t)b * TSEQ + qi) * NHEADS + h) * HDIM;
    #pragma unroll
    for (int d = 0; d < HDIM; d += 4) {
        float4 o;
        o.x = acc[d + 0] * inv_l;
        o.y = acc[d + 1] * inv_l;
        o.z = acc[d + 2] * inv_l;
        o.w = acc[d + 3] * inv_l;
        *(float4*)(op + d) = o;
    }
}

// ---------------- launch ----------------
extern "C" void kernel_launch(void* const* d_in, const int* in_sizes, int n_in,
                              void* d_out, int out_size)
{
    const float* x      = (const float*)d_in[0];
    const float* qkv_w  = (const float*)d_in[1];
    const float* qkv_b  = (const float*)d_in[2];
    const float* proj_w = (const float*)d_in[3];
    const float* proj_b = (const float*)d_in[4];
    float* out = (float*)d_out;

    // 1) QKV = x @ qkv_w^T + qkv_b
    qkv_gemm_kernel<<<dim3(QKV_N / BN, ROWS / BM), 256>>>(x, qkv_w, qkv_b);

    // 2) RoPE cos/sin table
    rope_table_kernel<<<(TSEQ * 32 + 255) / 256, 256>>>();

    // 3) RoPE apply + layout to [B,H,T,Dh]
    rope_apply_kernel<<<(BATCH * TSEQ * NHEADS * 32) / 256, 256>>>();

    // 4) causal flash attention
    flash_kernel<<<dim3(TSEQ / BQ, NHEADS, BATCH), BQ>>>();

    // 5) out = attn @ proj_w^T + proj_b
    proj_gemm_kernel<<<dim3(DMODEL / BN, ROWS / BM), 256>>>(proj_w, proj_b, out);
}